// round 16
// baseline (speedup 1.0000x reference)
#include <cuda_runtime.h>
#include <cuda_fp16.h>
#include <math.h>
#include <stdint.h>

#define B_    8
#define C_    256
#define HW_   9216
#define HEADS 8
#define CH    32
#define SPLITS 8

// ---------------- scratch ----------------
__device__ __align__(16) __half g_qh[(long)B_ * C_ * HW_];
__device__ __align__(16) __half g_kh[(long)B_ * C_ * HW_];
__device__ __align__(16) float g_Wqx[C_ * C_];
__device__ __align__(16) float g_Wqy[C_ * C_];
__device__ __align__(16) float g_bq[C_];
__device__ float g_ssq_q[B_ * C_];
__device__ float g_ssq_k[B_ * C_];
__device__ float g_Spart[B_ * HEADS * SPLITS * CH * CH];
__device__ float g_A[B_ * HEADS * CH * CH];
__device__ __align__(16) float g_Mf[B_ * C_ * C_];
__device__ __align__(16) float g_Wfin[B_ * C_ * C_];
__device__ float g_bfin[B_ * C_];
__device__ __align__(16) __half g_xyT[(long)B_ * HW_ * 512];
__device__ __align__(16) __half g_zT[(long)B_ * HW_ * 256];
__device__ __align__(16) __half g_WqA[256 * 512];
__device__ __align__(16) __half g_Wk[256 * 256];
__device__ __align__(16) __half g_WfA[B_ * 256 * 256];

// ---------------- helpers ----------------
__device__ __forceinline__ uint32_t smem_u32(const void* p) {
    uint32_t a;
    asm("{ .reg .u64 t; cvta.to.shared.u64 t, %1; cvt.u32.u64 %0, t; }" : "=r"(a) : "l"(p));
    return a;
}
__device__ __forceinline__ void cpasync16(uint32_t s, const void* g) {
    asm volatile("cp.async.cg.shared.global [%0], [%1], 16;" :: "r"(s), "l"(g));
}
__device__ __forceinline__ void ldsm_x4(uint32_t* r, uint32_t a) {
    asm volatile("ldmatrix.sync.aligned.m8n8.x4.shared.b16 {%0,%1,%2,%3}, [%4];"
        : "=r"(r[0]), "=r"(r[1]), "=r"(r[2]), "=r"(r[3]) : "r"(a));
}
__device__ __forceinline__ void ldsm_x2(uint32_t* r, uint32_t a) {
    asm volatile("ldmatrix.sync.aligned.m8n8.x2.shared.b16 {%0,%1}, [%2];"
        : "=r"(r[0]), "=r"(r[1]) : "r"(a));
}
__device__ __forceinline__ void mma_f16(float* d, const uint32_t* a, const uint32_t* b) {
    asm volatile("mma.sync.aligned.m16n8k16.row.col.f32.f16.f16.f32 "
        "{%0,%1,%2,%3}, {%4,%5,%6,%7}, {%8,%9}, {%0,%1,%2,%3};"
        : "+f"(d[0]), "+f"(d[1]), "+f"(d[2]), "+f"(d[3])
        : "r"(a[0]), "r"(a[1]), "r"(a[2]), "r"(a[3]), "r"(b[0]), "r"(b[1]));
}

#define SM_STRIDE 40
#define MAT_A (128 * SM_STRIDE)          // A tile: 128 rows
#define MAT_B (256 * SM_STRIDE)          // B tile: 256 rows
#define BUF_ELEMS (MAT_A + MAT_B)        // 15360 halves = 30720 B per stage
#define GSTAGE 3
#define SMEM_GEMM (GSTAGE * BUF_ELEMS * 2)   // 92160 bytes

// ---------------- HMMA fp16 GEMM: block 128m x 256n, warp 64x64, 3-stage ----------------
__global__ void __launch_bounds__(256, 1)
gemm_mma(const __half* __restrict__ Aw, long aStride, const __half* __restrict__ Bm,
         int K, const float* __restrict__ bias, int biasStride,
         float* __restrict__ out, __half* __restrict__ outh,
         const float* __restrict__ res, float* __restrict__ sumsq)
{
    extern __shared__ __half sm[];
    const int tid  = threadIdx.x;
    const int lane = tid & 31, wid = tid >> 5;
    const int warp_m = wid >> 2, warp_n = wid & 3;     // 2 x 4 warps, each 64m x 64n
    const int b  = blockIdx.z;
    const int m0 = blockIdx.x * 128, n0 = blockIdx.y * 256;

    const __half* gmA = Aw + (long)b * aStride + (long)m0 * K;
    const __half* gmB = Bm + ((long)b * HW_ + n0) * (long)K;

    const uint32_t smBase = smem_u32(sm);
    const int ldRow = tid >> 2;       // 0..63
    const int ldC16 = tid & 3;

    const int nch = K >> 5;

    // prologue: chunks 0,1 -> buffers 0,1
    #pragma unroll
    for (int pc = 0; pc < 2; pc++) {
        const uint32_t dst = smBase + (uint32_t)(pc * BUF_ELEMS * 2);
        #pragma unroll
        for (int i = 0; i < 2; i++) {
            int row = ldRow + i * 64;
            cpasync16(dst + (uint32_t)(row * SM_STRIDE + ldC16 * 8) * 2,
                      gmA + (long)row * K + pc * 32 + ldC16 * 8);
        }
        #pragma unroll
        for (int i = 0; i < 4; i++) {
            int row = ldRow + i * 64;
            cpasync16(dst + (uint32_t)(MAT_A + row * SM_STRIDE + ldC16 * 8) * 2,
                      gmB + (long)row * K + pc * 32 + ldC16 * 8);
        }
        asm volatile("cp.async.commit_group;" ::: "memory");
    }

    const int rowA = (lane & 7) + 8 * ((lane >> 3) & 1);
    const int colA = (lane >> 4) * 8;
    const int aoff = (warp_m * 64 + rowA) * SM_STRIDE + colA;
    // B x4 dual-k: lanes 16-31 address k+16
    const int bx4off = (warp_n * 64 + (lane & 7)) * SM_STRIDE
                     + 8 * ((lane >> 3) & 1) + 16 * ((lane >> 4) & 1);

    float d[4][8][4] = {};
    int bufc = 0;

    for (int c = 0; c < nch; c++) {
        if (c + 2 < nch) {
            int bufn = bufc + 2; if (bufn >= 3) bufn -= 3;
            const uint32_t nxt = smBase + (uint32_t)(bufn * BUF_ELEMS * 2);
            const int kc = (c + 2) << 5;
            #pragma unroll
            for (int i = 0; i < 2; i++) {
                int row = ldRow + i * 64;
                cpasync16(nxt + (uint32_t)(row * SM_STRIDE + ldC16 * 8) * 2,
                          gmA + (long)row * K + kc + ldC16 * 8);
            }
            #pragma unroll
            for (int i = 0; i < 4; i++) {
                int row = ldRow + i * 64;
                cpasync16(nxt + (uint32_t)(MAT_A + row * SM_STRIDE + ldC16 * 8) * 2,
                          gmB + (long)row * K + kc + ldC16 * 8);
            }
            asm volatile("cp.async.commit_group;" ::: "memory");
            asm volatile("cp.async.wait_group 2;" ::: "memory");
        } else if (c + 1 < nch) {
            asm volatile("cp.async.wait_group 1;" ::: "memory");
        } else {
            asm volatile("cp.async.wait_group 0;" ::: "memory");
        }
        __syncthreads();

        const uint32_t cur = smBase + (uint32_t)(bufc * BUF_ELEMS * 2);

        uint32_t bx4[8][4];
        #pragma unroll
        for (int nt = 0; nt < 8; nt++)
            ldsm_x4(bx4[nt], cur + (uint32_t)(MAT_A + bx4off + nt * 8 * SM_STRIDE) * 2);

        #pragma unroll
        for (int ks = 0; ks < 32; ks += 16) {
            uint32_t ahf[4][4];
            #pragma unroll
            for (int mt = 0; mt < 4; mt++)
                ldsm_x4(ahf[mt], cur + (uint32_t)(aoff + mt * 16 * SM_STRIDE + ks) * 2);
            const int bo = (ks >> 3);   // 0 or 2
            #pragma unroll
            for (int mt = 0; mt < 4; mt++)
                #pragma unroll
                for (int nt = 0; nt < 8; nt++)
                    mma_f16(d[mt][nt], ahf[mt], &bx4[nt][bo]);
        }
        __syncthreads();
        if (++bufc == 3) bufc = 0;
    }

    // epilogue
    const int mw = m0 + warp_m * 64;
    const int nw = n0 + warp_n * 64 + (lane & 3) * 2;
    #pragma unroll
    for (int mt = 0; mt < 4; mt++) {
        const int r0 = mw + mt * 16 + (lane >> 2);
        const int r1 = r0 + 8;
        const float bv0 = bias[b * biasStride + r0];
        const float bv1 = bias[b * biasStride + r1];
        const long base0 = ((long)b * C_ + r0) * HW_ + nw;
        const long base1 = ((long)b * C_ + r1) * HW_ + nw;
        float ss0 = 0.f, ss1 = 0.f;
        #pragma unroll
        for (int nt = 0; nt < 8; nt++) {
            float c0 = d[mt][nt][0] + bv0, c1 = d[mt][nt][1] + bv0;
            float c2 = d[mt][nt][2] + bv1, c3 = d[mt][nt][3] + bv1;
            if (res) {
                float2 ra = *(const float2*)&res[base0 + nt * 8];
                float2 rb = *(const float2*)&res[base1 + nt * 8];
                c0 += ra.x; c1 += ra.y; c2 += rb.x; c3 += rb.y;
            }
            ss0 += c0 * c0 + c1 * c1;
            ss1 += c2 * c2 + c3 * c3;
            if (outh) {
                *(__half2*)&outh[base0 + nt * 8] = __floats2half2_rn(c0, c1);
                *(__half2*)&outh[base1 + nt * 8] = __floats2half2_rn(c2, c3);
            } else {
                *(float2*)&out[base0 + nt * 8] = make_float2(c0, c1);
                *(float2*)&out[base1 + nt * 8] = make_float2(c2, c3);
            }
        }
        if (sumsq) {
            ss0 += __shfl_xor_sync(0xffffffffu, ss0, 1);
            ss0 += __shfl_xor_sync(0xffffffffu, ss0, 2);
            ss1 += __shfl_xor_sync(0xffffffffu, ss1, 1);
            ss1 += __shfl_xor_sync(0xffffffffu, ss1, 2);
            if ((lane & 3) == 0) {
                atomicAdd(&sumsq[b * C_ + r0], ss0);
                atomicAdd(&sumsq[b * C_ + r1], ss1);
            }
        }
    }
}

// ---------------- attn via HMMA: partial S = q . k^T ----------------
#define AST 72
#define ATILE (32 * AST)
#define ABUF  (2 * ATILE)
#define ANSTAGE 4
__global__ void __launch_bounds__(128)
attn_s_mma() {
    __shared__ __half smq[ANSTAGE * ABUF];   // 36864 bytes
    const int h = blockIdx.x, b = blockIdx.y, sp = blockIdx.z;
    const int tid = threadIdx.x;
    const int lane = tid & 31, wid = tid >> 5;
    const int p0 = sp * (HW_ / SPLITS);
    const __half* qb = g_qh + ((long)b * C_ + h * CH) * HW_ + p0;
    const __half* kb = g_kh + ((long)b * C_ + h * CH) * HW_ + p0;

    const uint32_t smBase = smem_u32(smq);
    const int nch = (HW_ / SPLITS) >> 6;

    #pragma unroll
    for (int pc = 0; pc < 3; pc++) {
        const uint32_t dst = smBase + (uint32_t)(pc * ABUF * 2);
        #pragma unroll
        for (int i = 0; i < 2; i++) {
            int slot = tid + i * 128;
            int row = slot >> 3, c16 = slot & 7;
            long go = (long)row * HW_ + pc * 64 + c16 * 8;
            cpasync16(dst + (uint32_t)(row * AST + c16 * 8) * 2, qb + go);
            cpasync16(dst + (uint32_t)(ATILE + row * AST + c16 * 8) * 2, kb + go);
        }
        asm volatile("cp.async.commit_group;" ::: "memory");
    }

    const int rowA = (lane & 7) + 8 * ((lane >> 3) & 1);
    const int colA = (lane >> 4) * 8;
    const int boffw = (wid * 8 + (lane & 7)) * AST + 8 * ((lane >> 3) & 1);

    float d[2][4] = {};

    for (int c = 0; c < nch; c++) {
        if (c + 3 < nch) {
            const uint32_t nxt = smBase + (uint32_t)(((c + 3) & 3) * ABUF * 2);
            const int kc = (c + 3) << 6;
            #pragma unroll
            for (int i = 0; i < 2; i++) {
                int slot = tid + i * 128;
                int row = slot >> 3, c16 = slot & 7;
                long go = (long)row * HW_ + kc + c16 * 8;
                cpasync16(nxt + (uint32_t)(row * AST + c16 * 8) * 2, qb + go);
                cpasync16(nxt + (uint32_t)(ATILE + row * AST + c16 * 8) * 2, kb + go);
            }
            asm volatile("cp.async.commit_group;" ::: "memory");
            asm volatile("cp.async.wait_group 3;" ::: "memory");
        } else if (c + 2 < nch) {
            asm volatile("cp.async.wait_group 2;" ::: "memory");
        } else if (c + 1 < nch) {
            asm volatile("cp.async.wait_group 1;" ::: "memory");
        } else {
            asm volatile("cp.async.wait_group 0;" ::: "memory");
        }
        __syncthreads();

        const uint32_t cur = smBase + (uint32_t)((c & 3) * ABUF * 2);
        #pragma unroll
        for (int ks = 0; ks < 64; ks += 16) {
            uint32_t af[2][4], bf[2];
            ldsm_x4(af[0], cur + (uint32_t)(rowA * AST + colA + ks) * 2);
            ldsm_x4(af[1], cur + (uint32_t)((16 + rowA) * AST + colA + ks) * 2);
            ldsm_x2(bf, cur + (uint32_t)(ATILE + boffw + ks) * 2);
            mma_f16(d[0], af[0], bf);
            mma_f16(d[1], af[1], bf);
        }
        __syncthreads();
    }

    float* Sp = g_Spart + ((long)(b * HEADS + h) * SPLITS + sp) * (CH * CH);
    const int dc = wid * 8 + (lane & 3) * 2;
    #pragma unroll
    for (int mt = 0; mt < 2; mt++) {
        int c0 = mt * 16 + (lane >> 2);
        Sp[c0 * CH + dc]           = d[mt][0];
        Sp[c0 * CH + dc + 1]       = d[mt][1];
        Sp[(c0 + 8) * CH + dc]     = d[mt][2];
        Sp[(c0 + 8) * CH + dc + 1] = d[mt][3];
    }
}

// ---------------- convert: x,y,z -> transposed fp16 ----------------
__global__ void convert_T(const float* __restrict__ x, const float* __restrict__ y,
                          const float* __restrict__ z) {
    __shared__ float sm[32][68];
    const int nt = blockIdx.x, ct = blockIdx.y;
    const int b = blockIdx.z / 3, t = blockIdx.z % 3;
    const float* src = (t == 0 ? x : (t == 1 ? y : z)) + (long)b * C_ * HW_;
    const int tid = threadIdx.x;

    {
        const int c = tid >> 3, colg = (tid & 7) * 8;
        const float* p = &src[(long)(ct * 32 + c) * HW_ + nt * 64 + colg];
        float4 v0 = *(const float4*)p;
        float4 v1 = *(const float4*)(p + 4);
        *(float4*)&sm[c][colg]     = v0;
        *(float4*)&sm[c][colg + 4] = v1;
    }
    __syncthreads();

    __half* dh = (t == 2) ? g_zT : g_xyT;
    const int dk = (t == 2) ? 256 : 512;
    const int off = ((t == 1) ? 256 : 0) + ct * 32;

    const int n = tid >> 2, part = (tid & 3) * 8;
    __half2 h[4];
    #pragma unroll
    for (int i = 0; i < 4; i++)
        h[i] = __floats2half2_rn(sm[part + 2 * i][n], sm[part + 2 * i + 1][n]);
    long idx = ((long)b * HW_ + (long)nt * 64 + n) * dk + off + part;
    *(uint4*)&dh[idx] = *(uint4*)h;
}

// ---------------- weight converts ----------------
__global__ void cvtK_w(const float* __restrict__ Wkf) {
    const int i = blockIdx.x * 256 + threadIdx.x;
    g_Wk[i] = __float2half(Wkf[i]);
}
__global__ void cvtQ_w() {
    const int job = blockIdx.y;
    const int i = blockIdx.x * 256 + threadIdx.x;
    const int r = i >> 8, c = i & 255;
    g_WqA[r * 512 + job * 256 + c] = __float2half(job == 0 ? g_Wqx[i] : g_Wqy[i]);
}
__global__ void cvtF_w() {
    const int i = blockIdx.x * 256 + threadIdx.x;
    g_WfA[i] = __float2half(g_Wfin[i]);
}

__global__ void zero_kernel() {
    int i = blockIdx.x * blockDim.x + threadIdx.x;
    if (i < B_ * C_) { g_ssq_q[i] = 0.f; g_ssq_k[i] = 0.f; }
}

__global__ void fold_weights(const float* __restrict__ Wcat, const float* __restrict__ Wqr,
                             const float* __restrict__ Wqd, const float* __restrict__ bqr,
                             const float* __restrict__ bqd, const float* __restrict__ bcat) {
    int o  = blockIdx.x;
    int ci = threadIdx.x;
    float sx = 0.f, sy = 0.f;
    #pragma unroll 8
    for (int j = 0; j < 128; j++) {
        float wl = Wcat[o * 256 + j];
        float wr = Wcat[o * 256 + 128 + j];
        sx += wl * Wqr[j * 256 + ci];
        sy += wr * Wqd[j * 256 + ci];
    }
    g_Wqx[o * 256 + ci] = sx;
    g_Wqy[o * 256 + ci] = sy;
    if (ci == 0) {
        float s = bcat[o];
        for (int j = 0; j < 128; j++)
            s += Wcat[o * 256 + j] * bqr[j] + Wcat[o * 256 + 128 + j] * bqd[j];
        g_bq[o] = s;
    }
}

__global__ void softmax_kernel(const float* __restrict__ temp) {
    int bh = blockIdx.x;
    int b = bh / HEADS, h = bh % HEADS;
    int c = threadIdx.x;
    float iq = 1.f / fmaxf(sqrtf(g_ssq_q[b * C_ + h * CH + c]), 1e-12f);
    float t  = temp[h];
    float row[CH];
    float mx = -1e30f;
    #pragma unroll
    for (int d = 0; d < CH; d++) {
        float s = 0.f;
        #pragma unroll
        for (int sp = 0; sp < SPLITS; sp++)
            s += g_Spart[((long)bh * SPLITS + sp) * (CH * CH) + c * CH + d];
        float ik = 1.f / fmaxf(sqrtf(g_ssq_k[b * C_ + h * CH + d]), 1e-12f);
        s *= iq * ik * t;
        row[d] = s;
        mx = fmaxf(mx, s);
    }
    float sum = 0.f;
    #pragma unroll
    for (int d = 0; d < CH; d++) { row[d] = expf(row[d] - mx); sum += row[d]; }
    float inv = 1.f / sum;
    #pragma unroll
    for (int d = 0; d < CH; d++)
        g_A[(long)bh * (CH * CH) + c * CH + d] = row[d] * inv;
}

__global__ void mfuse_kernel(const float* __restrict__ Wproj) {
    int h = blockIdx.x, b = blockIdx.y;
    __shared__ float As[CH][CH + 1];
    int tid = threadIdx.x;
    for (int i = tid; i < CH * CH; i += 256)
        As[i >> 5][i & 31] = g_A[(long)(b * HEADS + h) * (CH * CH) + i];
    __syncthreads();
    int c = tid;
    float w[CH];
    #pragma unroll
    for (int e = 0; e < CH; e++) w[e] = Wproj[c * 256 + h * CH + e];
    #pragma unroll 4
    for (int d = 0; d < CH; d++) {
        float s = 0.f;
        #pragma unroll
        for (int e = 0; e < CH; e++) s = fmaf(w[e], As[e][d], s);
        g_Mf[((long)b * C_ + c) * C_ + h * CH + d] = s;
    }
}

__global__ void wfinal_kernel(const float* __restrict__ Wv, const float* __restrict__ bv,
                              const float* __restrict__ bproj) {
    __shared__ float mr[8][256];
    const int b = blockIdx.y, c0 = blockIdx.x * 8;
    const int d = threadIdx.x;
    #pragma unroll
    for (int r = 0; r < 8; r++)
        mr[r][d] = g_Mf[((long)b * C_ + c0 + r) * C_ + d];
    __syncthreads();
    float acc[8] = {};
    for (int e = 0; e < 256; e++) {
        float wv = Wv[e * 256 + d];
        #pragma unroll
        for (int r = 0; r < 8; r++) acc[r] = fmaf(mr[r][e], wv, acc[r]);
    }
    #pragma unroll
    for (int r = 0; r < 8; r++)
        g_Wfin[((long)b * C_ + c0 + r) * C_ + d] = acc[r];
    if (d < 8) {
        float bb = bproj[c0 + d];
        for (int e = 0; e < 256; e++) bb += mr[d][e] * bv[e];
        g_bfin[b * C_ + c0 + d] = bb;
    }
}

// ---------------- launch ----------------
extern "C" void kernel_launch(void* const* d_in, const int* in_sizes, int n_in,
                              void* d_out, int out_size) {
    const float* x      = (const float*)d_in[0];
    const float* y      = (const float*)d_in[1];
    const float* z      = (const float*)d_in[2];
    const float* W_qr   = (const float*)d_in[3];
    const float* b_qr   = (const float*)d_in[4];
    const float* W_qd   = (const float*)d_in[5];
    const float* b_qd   = (const float*)d_in[6];
    const float* W_kf   = (const float*)d_in[7];
    const float* b_kf   = (const float*)d_in[8];
    const float* W_vf   = (const float*)d_in[9];
    const float* b_vf   = (const float*)d_in[10];
    const float* W_cat  = (const float*)d_in[11];
    const float* b_cat  = (const float*)d_in[12];
    const float* W_proj = (const float*)d_in[13];
    const float* b_proj = (const float*)d_in[14];
    const float* temp   = (const float*)d_in[15];
    float* out = (float*)d_out;

    float *p_bq, *p_ssq, *p_ssk, *p_bfin;
    __half *p_qh, *p_kh, *p_xyT, *p_zT, *p_WqA, *p_Wk, *p_WfA;
    cudaGetSymbolAddress((void**)&p_qh,   g_qh);
    cudaGetSymbolAddress((void**)&p_kh,   g_kh);
    cudaGetSymbolAddress((void**)&p_bq,   g_bq);
    cudaGetSymbolAddress((void**)&p_ssq,  g_ssq_q);
    cudaGetSymbolAddress((void**)&p_ssk,  g_ssq_k);
    cudaGetSymbolAddress((void**)&p_bfin, g_bfin);
    cudaGetSymbolAddress((void**)&p_xyT,  g_xyT);
    cudaGetSymbolAddress((void**)&p_zT,   g_zT);
    cudaGetSymbolAddress((void**)&p_WqA,  g_WqA);
    cudaGetSymbolAddress((void**)&p_Wk,   g_Wk);
    cudaGetSymbolAddress((void**)&p_WfA,  g_WfA);

    cudaFuncSetAttribute(gemm_mma, cudaFuncAttributeMaxDynamicSharedMemorySize, SMEM_GEMM);

    dim3 gg(C_ / 128, HW_ / 256, B_);   // (2, 36, 8)

    convert_T<<<dim3(HW_ / 64, C_ / 32, B_ * 3), 256>>>(x, y, z);              // 0
    cvtK_w<<<256, 256>>>(W_kf);                                                // 1
    zero_kernel<<<(B_ * C_ + 255) / 256, 256>>>();                             // 2
    gemm_mma<<<gg, 256, SMEM_GEMM>>>(p_Wk, 0, p_zT, 256,                       // 3
                                     b_kf, 0, nullptr, p_kh, nullptr, p_ssk);
    fold_weights<<<256, 256>>>(W_cat, W_qr, W_qd, b_qr, b_qd, b_cat);          // 4
    cvtQ_w<<<dim3(256, 2), 256>>>();                                           // 5
    gemm_mma<<<gg, 256, SMEM_GEMM>>>(p_WqA, 0, p_xyT, 512,                     // 6
                                     p_bq, 0, nullptr, p_qh, nullptr, p_ssq);

    attn_s_mma<<<dim3(HEADS, B_, SPLITS), 128>>>();
    softmax_kernel<<<B_ * HEADS, 32>>>(temp);
    mfuse_kernel<<<dim3(HEADS, B_), 256>>>(W_proj);
    wfinal_kernel<<<dim3(32, B_), 256>>>(W_vf, b_vf, b_proj);
    cvtF_w<<<B_ * 256, 256>>>();

    gemm_mma<<<gg, 256, SMEM_GEMM>>>(p_WfA, (long)C_ * C_, p_zT, 256,
                                     p_bfin, C_, out, nullptr, z, nullptr);
}

// round 17
// speedup vs baseline: 1.1016x; 1.1016x over previous
#include <cuda_runtime.h>
#include <cuda_fp16.h>
#include <math.h>
#include <stdint.h>

#define B_    8
#define C_    256
#define HW_   9216
#define HEADS 8
#define CH    32
#define SPLITS 8

// ---------------- scratch ----------------
__device__ __align__(16) __half g_qh[(long)B_ * C_ * HW_];
__device__ __align__(16) __half g_kh[(long)B_ * C_ * HW_];
__device__ __align__(16) float g_Wqx[C_ * C_];
__device__ __align__(16) float g_Wqy[C_ * C_];
__device__ __align__(16) float g_bq[C_];
__device__ float g_ssq_q[B_ * C_];
__device__ float g_ssq_k[B_ * C_];
__device__ float g_Spart[B_ * HEADS * SPLITS * CH * CH];
__device__ float g_A[B_ * HEADS * CH * CH];
__device__ __align__(16) float g_Mf[B_ * C_ * C_];
__device__ __align__(16) float g_Wfin[B_ * C_ * C_];
__device__ float g_bfin[B_ * C_];
__device__ __align__(16) __half g_xyT[(long)B_ * HW_ * 512];
__device__ __align__(16) __half g_zT[(long)B_ * HW_ * 256];
__device__ __align__(16) __half g_WqA[256 * 512];
__device__ __align__(16) __half g_Wk[256 * 256];
__device__ __align__(16) __half g_WfA[B_ * 256 * 256];

// ---------------- helpers ----------------
__device__ __forceinline__ uint32_t smem_u32(const void* p) {
    uint32_t a;
    asm("{ .reg .u64 t; cvta.to.shared.u64 t, %1; cvt.u32.u64 %0, t; }" : "=r"(a) : "l"(p));
    return a;
}
__device__ __forceinline__ void cpasync16(uint32_t s, const void* g) {
    asm volatile("cp.async.cg.shared.global [%0], [%1], 16;" :: "r"(s), "l"(g));
}
__device__ __forceinline__ void ldsm_x4(uint32_t* r, uint32_t a) {
    asm volatile("ldmatrix.sync.aligned.m8n8.x4.shared.b16 {%0,%1,%2,%3}, [%4];"
        : "=r"(r[0]), "=r"(r[1]), "=r"(r[2]), "=r"(r[3]) : "r"(a));
}
__device__ __forceinline__ void ldsm_x2(uint32_t* r, uint32_t a) {
    asm volatile("ldmatrix.sync.aligned.m8n8.x2.shared.b16 {%0,%1}, [%2];"
        : "=r"(r[0]), "=r"(r[1]) : "r"(a));
}
__device__ __forceinline__ void mma_f16(float* d, const uint32_t* a, const uint32_t* b) {
    asm volatile("mma.sync.aligned.m16n8k16.row.col.f32.f16.f16.f32 "
        "{%0,%1,%2,%3}, {%4,%5,%6,%7}, {%8,%9}, {%0,%1,%2,%3};"
        : "+f"(d[0]), "+f"(d[1]), "+f"(d[2]), "+f"(d[3])
        : "r"(a[0]), "r"(a[1]), "r"(a[2]), "r"(a[3]), "r"(b[0]), "r"(b[1]));
}

// k-chunk = 64 halves/row, row stride 72 (144B = 9*16B)
#define SM_STRIDE 72
#define MAT_ELEMS (128 * SM_STRIDE)        // 9216 halves per matrix per stage
#define BUF_ELEMS (2 * MAT_ELEMS)
#define GSTAGE 2
#define SMEM_GEMM (GSTAGE * BUF_ELEMS * 2) // 73728 bytes

// ---------------- HMMA fp16 GEMM: block 128x128, warp 64x32, chunk 64k, 2-stage ----------------
__global__ void __launch_bounds__(256, 2)
gemm_mma(const __half* __restrict__ Aw, long aStride, const __half* __restrict__ Bm,
         int K, const float* __restrict__ bias, int biasStride,
         float* __restrict__ out, __half* __restrict__ outh,
         const float* __restrict__ res, float* __restrict__ sumsq)
{
    extern __shared__ __half sm[];
    const int tid  = threadIdx.x;
    const int lane = tid & 31, wid = tid >> 5;
    const int warp_m = wid >> 2, warp_n = wid & 3;
    const int b  = blockIdx.z;
    const int m0 = blockIdx.x * 128, n0 = blockIdx.y * 128;

    const __half* gmA = Aw + (long)b * aStride + (long)m0 * K;
    const __half* gmB = Bm + ((long)b * HW_ + n0) * (long)K;

    const uint32_t smBase = smem_u32(sm);
    const int ldRow = tid >> 3;        // 0..31 (over 4 iters -> 128 rows)
    const int ldC16 = tid & 7;         // 8 x 16B per 64-half row

    const int nch = K >> 6;            // chunks of 64

    // prologue: chunk 0 -> buffer 0
    {
        const uint32_t dst = smBase;
        #pragma unroll
        for (int i = 0; i < 4; i++) {
            int row = ldRow + i * 32;
            cpasync16(dst + (uint32_t)(row * SM_STRIDE + ldC16 * 8) * 2,
                      gmA + (long)row * K + ldC16 * 8);
            cpasync16(dst + (uint32_t)(MAT_ELEMS + row * SM_STRIDE + ldC16 * 8) * 2,
                      gmB + (long)row * K + ldC16 * 8);
        }
        asm volatile("cp.async.commit_group;" ::: "memory");
    }

    const int rowA = (lane & 7) + 8 * ((lane >> 3) & 1);
    const int colA = (lane >> 4) * 8;
    const int aoff = (warp_m * 64 + rowA) * SM_STRIDE + colA;
    // B x4 dual-k: lanes 16-31 address k+16
    const int bx4off = (warp_n * 32 + (lane & 7)) * SM_STRIDE
                     + 8 * ((lane >> 3) & 1) + 16 * ((lane >> 4) & 1);

    float d[4][4][4] = {};

    for (int c = 0; c < nch; c++) {
        if (c + 1 < nch) {
            const uint32_t nxt = smBase + (uint32_t)(((c + 1) & 1) * BUF_ELEMS * 2);
            const int kc = (c + 1) << 6;
            #pragma unroll
            for (int i = 0; i < 4; i++) {
                int row = ldRow + i * 32;
                cpasync16(nxt + (uint32_t)(row * SM_STRIDE + ldC16 * 8) * 2,
                          gmA + (long)row * K + kc + ldC16 * 8);
                cpasync16(nxt + (uint32_t)(MAT_ELEMS + row * SM_STRIDE + ldC16 * 8) * 2,
                          gmB + (long)row * K + kc + ldC16 * 8);
            }
            asm volatile("cp.async.commit_group;" ::: "memory");
            asm volatile("cp.async.wait_group 1;" ::: "memory");
        } else {
            asm volatile("cp.async.wait_group 0;" ::: "memory");
        }
        __syncthreads();

        const uint32_t cur = smBase + (uint32_t)((c & 1) * BUF_ELEMS * 2);

        // B fragments: 4 nt x 2 k-sets (each x4 covers k, k+16)
        uint32_t bx4[4][2][4];
        #pragma unroll
        for (int nt = 0; nt < 4; nt++) {
            ldsm_x4(bx4[nt][0], cur + (uint32_t)(MAT_ELEMS + bx4off + nt * 8 * SM_STRIDE) * 2);
            ldsm_x4(bx4[nt][1], cur + (uint32_t)(MAT_ELEMS + bx4off + nt * 8 * SM_STRIDE + 32) * 2);
        }

        #pragma unroll
        for (int ks = 0; ks < 4; ks++) {          // 4 x 16-k steps
            uint32_t ahf[4][4];
            #pragma unroll
            for (int mt = 0; mt < 4; mt++)
                ldsm_x4(ahf[mt], cur + (uint32_t)(aoff + mt * 16 * SM_STRIDE + ks * 16) * 2);
            const int st = ks >> 1, bo = (ks & 1) * 2;
            #pragma unroll
            for (int mt = 0; mt < 4; mt++)
                #pragma unroll
                for (int nt = 0; nt < 4; nt++)
                    mma_f16(d[mt][nt], ahf[mt], &bx4[nt][st][bo]);
        }
        __syncthreads();
    }

    // epilogue
    const int mw = m0 + warp_m * 64;
    const int nw = n0 + warp_n * 32 + (lane & 3) * 2;
    #pragma unroll
    for (int mt = 0; mt < 4; mt++) {
        const int r0 = mw + mt * 16 + (lane >> 2);
        const int r1 = r0 + 8;
        const float bv0 = bias[b * biasStride + r0];
        const float bv1 = bias[b * biasStride + r1];
        const long base0 = ((long)b * C_ + r0) * HW_ + nw;
        const long base1 = ((long)b * C_ + r1) * HW_ + nw;
        float ss0 = 0.f, ss1 = 0.f;
        #pragma unroll
        for (int nt = 0; nt < 4; nt++) {
            float c0 = d[mt][nt][0] + bv0, c1 = d[mt][nt][1] + bv0;
            float c2 = d[mt][nt][2] + bv1, c3 = d[mt][nt][3] + bv1;
            if (res) {
                float2 ra = *(const float2*)&res[base0 + nt * 8];
                float2 rb = *(const float2*)&res[base1 + nt * 8];
                c0 += ra.x; c1 += ra.y; c2 += rb.x; c3 += rb.y;
            }
            ss0 += c0 * c0 + c1 * c1;
            ss1 += c2 * c2 + c3 * c3;
            if (outh) {
                *(__half2*)&outh[base0 + nt * 8] = __floats2half2_rn(c0, c1);
                *(__half2*)&outh[base1 + nt * 8] = __floats2half2_rn(c2, c3);
            } else {
                *(float2*)&out[base0 + nt * 8] = make_float2(c0, c1);
                *(float2*)&out[base1 + nt * 8] = make_float2(c2, c3);
            }
        }
        if (sumsq) {
            ss0 += __shfl_xor_sync(0xffffffffu, ss0, 1);
            ss0 += __shfl_xor_sync(0xffffffffu, ss0, 2);
            ss1 += __shfl_xor_sync(0xffffffffu, ss1, 1);
            ss1 += __shfl_xor_sync(0xffffffffu, ss1, 2);
            if ((lane & 3) == 0) {
                atomicAdd(&sumsq[b * C_ + r0], ss0);
                atomicAdd(&sumsq[b * C_ + r1], ss1);
            }
        }
    }
}

// ---------------- attn via HMMA: partial S = q . k^T ----------------
#define AST 72
#define ATILE (32 * AST)
#define ABUF  (2 * ATILE)
#define ANSTAGE 4
__global__ void __launch_bounds__(128)
attn_s_mma() {
    __shared__ __half smq[ANSTAGE * ABUF];   // 36864 bytes
    const int h = blockIdx.x, b = blockIdx.y, sp = blockIdx.z;
    const int tid = threadIdx.x;
    const int lane = tid & 31, wid = tid >> 5;
    const int p0 = sp * (HW_ / SPLITS);
    const __half* qb = g_qh + ((long)b * C_ + h * CH) * HW_ + p0;
    const __half* kb = g_kh + ((long)b * C_ + h * CH) * HW_ + p0;

    const uint32_t smBase = smem_u32(smq);
    const int nch = (HW_ / SPLITS) >> 6;

    #pragma unroll
    for (int pc = 0; pc < 3; pc++) {
        const uint32_t dst = smBase + (uint32_t)(pc * ABUF * 2);
        #pragma unroll
        for (int i = 0; i < 2; i++) {
            int slot = tid + i * 128;
            int row = slot >> 3, c16 = slot & 7;
            long go = (long)row * HW_ + pc * 64 + c16 * 8;
            cpasync16(dst + (uint32_t)(row * AST + c16 * 8) * 2, qb + go);
            cpasync16(dst + (uint32_t)(ATILE + row * AST + c16 * 8) * 2, kb + go);
        }
        asm volatile("cp.async.commit_group;" ::: "memory");
    }

    const int rowA = (lane & 7) + 8 * ((lane >> 3) & 1);
    const int colA = (lane >> 4) * 8;
    const int boffw = (wid * 8 + (lane & 7)) * AST + 8 * ((lane >> 3) & 1);

    float d[2][4] = {};

    for (int c = 0; c < nch; c++) {
        if (c + 3 < nch) {
            const uint32_t nxt = smBase + (uint32_t)(((c + 3) & 3) * ABUF * 2);
            const int kc = (c + 3) << 6;
            #pragma unroll
            for (int i = 0; i < 2; i++) {
                int slot = tid + i * 128;
                int row = slot >> 3, c16 = slot & 7;
                long go = (long)row * HW_ + kc + c16 * 8;
                cpasync16(nxt + (uint32_t)(row * AST + c16 * 8) * 2, qb + go);
                cpasync16(nxt + (uint32_t)(ATILE + row * AST + c16 * 8) * 2, kb + go);
            }
            asm volatile("cp.async.commit_group;" ::: "memory");
            asm volatile("cp.async.wait_group 3;" ::: "memory");
        } else if (c + 2 < nch) {
            asm volatile("cp.async.wait_group 2;" ::: "memory");
        } else if (c + 1 < nch) {
            asm volatile("cp.async.wait_group 1;" ::: "memory");
        } else {
            asm volatile("cp.async.wait_group 0;" ::: "memory");
        }
        __syncthreads();

        const uint32_t cur = smBase + (uint32_t)((c & 3) * ABUF * 2);
        #pragma unroll
        for (int ks = 0; ks < 64; ks += 16) {
            uint32_t af[2][4], bf[2];
            ldsm_x4(af[0], cur + (uint32_t)(rowA * AST + colA + ks) * 2);
            ldsm_x4(af[1], cur + (uint32_t)((16 + rowA) * AST + colA + ks) * 2);
            ldsm_x2(bf, cur + (uint32_t)(ATILE + boffw + ks) * 2);
            mma_f16(d[0], af[0], bf);
            mma_f16(d[1], af[1], bf);
        }
        __syncthreads();
    }

    float* Sp = g_Spart + ((long)(b * HEADS + h) * SPLITS + sp) * (CH * CH);
    const int dc = wid * 8 + (lane & 3) * 2;
    #pragma unroll
    for (int mt = 0; mt < 2; mt++) {
        int c0 = mt * 16 + (lane >> 2);
        Sp[c0 * CH + dc]           = d[mt][0];
        Sp[c0 * CH + dc + 1]       = d[mt][1];
        Sp[(c0 + 8) * CH + dc]     = d[mt][2];
        Sp[(c0 + 8) * CH + dc + 1] = d[mt][3];
    }
}

// ---------------- convert: x,y,z -> transposed fp16 ----------------
__global__ void convert_T(const float* __restrict__ x, const float* __restrict__ y,
                          const float* __restrict__ z) {
    __shared__ float sm[32][68];
    const int nt = blockIdx.x, ct = blockIdx.y;
    const int b = blockIdx.z / 3, t = blockIdx.z % 3;
    const float* src = (t == 0 ? x : (t == 1 ? y : z)) + (long)b * C_ * HW_;
    const int tid = threadIdx.x;

    {
        const int c = tid >> 3, colg = (tid & 7) * 8;
        const float* p = &src[(long)(ct * 32 + c) * HW_ + nt * 64 + colg];
        float4 v0 = *(const float4*)p;
        float4 v1 = *(const float4*)(p + 4);
        *(float4*)&sm[c][colg]     = v0;
        *(float4*)&sm[c][colg + 4] = v1;
    }
    __syncthreads();

    __half* dh = (t == 2) ? g_zT : g_xyT;
    const int dk = (t == 2) ? 256 : 512;
    const int off = ((t == 1) ? 256 : 0) + ct * 32;

    const int n = tid >> 2, part = (tid & 3) * 8;
    __half2 h[4];
    #pragma unroll
    for (int i = 0; i < 4; i++)
        h[i] = __floats2half2_rn(sm[part + 2 * i][n], sm[part + 2 * i + 1][n]);
    long idx = ((long)b * HW_ + (long)nt * 64 + n) * dk + off + part;
    *(uint4*)&dh[idx] = *(uint4*)h;
}

// ---------------- weight converts ----------------
__global__ void cvtK_w(const float* __restrict__ Wkf) {
    const int i = blockIdx.x * 256 + threadIdx.x;
    g_Wk[i] = __float2half(Wkf[i]);
}
__global__ void cvtQ_w() {
    const int job = blockIdx.y;
    const int i = blockIdx.x * 256 + threadIdx.x;
    const int r = i >> 8, c = i & 255;
    g_WqA[r * 512 + job * 256 + c] = __float2half(job == 0 ? g_Wqx[i] : g_Wqy[i]);
}
__global__ void cvtF_w() {
    const int i = blockIdx.x * 256 + threadIdx.x;
    g_WfA[i] = __float2half(g_Wfin[i]);
}

__global__ void zero_kernel() {
    int i = blockIdx.x * blockDim.x + threadIdx.x;
    if (i < B_ * C_) { g_ssq_q[i] = 0.f; g_ssq_k[i] = 0.f; }
}

__global__ void fold_weights(const float* __restrict__ Wcat, const float* __restrict__ Wqr,
                             const float* __restrict__ Wqd, const float* __restrict__ bqr,
                             const float* __restrict__ bqd, const float* __restrict__ bcat) {
    int o  = blockIdx.x;
    int ci = threadIdx.x;
    float sx = 0.f, sy = 0.f;
    #pragma unroll 8
    for (int j = 0; j < 128; j++) {
        float wl = Wcat[o * 256 + j];
        float wr = Wcat[o * 256 + 128 + j];
        sx += wl * Wqr[j * 256 + ci];
        sy += wr * Wqd[j * 256 + ci];
    }
    g_Wqx[o * 256 + ci] = sx;
    g_Wqy[o * 256 + ci] = sy;
    if (ci == 0) {
        float s = bcat[o];
        for (int j = 0; j < 128; j++)
            s += Wcat[o * 256 + j] * bqr[j] + Wcat[o * 256 + 128 + j] * bqd[j];
        g_bq[o] = s;
    }
}

__global__ void softmax_kernel(const float* __restrict__ temp) {
    int bh = blockIdx.x;
    int b = bh / HEADS, h = bh % HEADS;
    int c = threadIdx.x;
    float iq = 1.f / fmaxf(sqrtf(g_ssq_q[b * C_ + h * CH + c]), 1e-12f);
    float t  = temp[h];
    float row[CH];
    float mx = -1e30f;
    #pragma unroll
    for (int d = 0; d < CH; d++) {
        float s = 0.f;
        #pragma unroll
        for (int sp = 0; sp < SPLITS; sp++)
            s += g_Spart[((long)bh * SPLITS + sp) * (CH * CH) + c * CH + d];
        float ik = 1.f / fmaxf(sqrtf(g_ssq_k[b * C_ + h * CH + d]), 1e-12f);
        s *= iq * ik * t;
        row[d] = s;
        mx = fmaxf(mx, s);
    }
    float sum = 0.f;
    #pragma unroll
    for (int d = 0; d < CH; d++) { row[d] = expf(row[d] - mx); sum += row[d]; }
    float inv = 1.f / sum;
    #pragma unroll
    for (int d = 0; d < CH; d++)
        g_A[(long)bh * (CH * CH) + c * CH + d] = row[d] * inv;
}

__global__ void mfuse_kernel(const float* __restrict__ Wproj) {
    int h = blockIdx.x, b = blockIdx.y;
    __shared__ float As[CH][CH + 1];
    int tid = threadIdx.x;
    for (int i = tid; i < CH * CH; i += 256)
        As[i >> 5][i & 31] = g_A[(long)(b * HEADS + h) * (CH * CH) + i];
    __syncthreads();
    int c = tid;
    float w[CH];
    #pragma unroll
    for (int e = 0; e < CH; e++) w[e] = Wproj[c * 256 + h * CH + e];
    #pragma unroll 4
    for (int d = 0; d < CH; d++) {
        float s = 0.f;
        #pragma unroll
        for (int e = 0; e < CH; e++) s = fmaf(w[e], As[e][d], s);
        g_Mf[((long)b * C_ + c) * C_ + h * CH + d] = s;
    }
}

__global__ void wfinal_kernel(const float* __restrict__ Wv, const float* __restrict__ bv,
                              const float* __restrict__ bproj) {
    __shared__ float mr[8][256];
    const int b = blockIdx.y, c0 = blockIdx.x * 8;
    const int d = threadIdx.x;
    #pragma unroll
    for (int r = 0; r < 8; r++)
        mr[r][d] = g_Mf[((long)b * C_ + c0 + r) * C_ + d];
    __syncthreads();
    float acc[8] = {};
    for (int e = 0; e < 256; e++) {
        float wv = Wv[e * 256 + d];
        #pragma unroll
        for (int r = 0; r < 8; r++) acc[r] = fmaf(mr[r][e], wv, acc[r]);
    }
    #pragma unroll
    for (int r = 0; r < 8; r++)
        g_Wfin[((long)b * C_ + c0 + r) * C_ + d] = acc[r];
    if (d < 8) {
        float bb = bproj[c0 + d];
        for (int e = 0; e < 256; e++) bb += mr[d][e] * bv[e];
        g_bfin[b * C_ + c0 + d] = bb;
    }
}

// ---------------- launch ----------------
extern "C" void kernel_launch(void* const* d_in, const int* in_sizes, int n_in,
                              void* d_out, int out_size) {
    const float* x      = (const float*)d_in[0];
    const float* y      = (const float*)d_in[1];
    const float* z      = (const float*)d_in[2];
    const float* W_qr   = (const float*)d_in[3];
    const float* b_qr   = (const float*)d_in[4];
    const float* W_qd   = (const float*)d_in[5];
    const float* b_qd   = (const float*)d_in[6];
    const float* W_kf   = (const float*)d_in[7];
    const float* b_kf   = (const float*)d_in[8];
    const float* W_vf   = (const float*)d_in[9];
    const float* b_vf   = (const float*)d_in[10];
    const float* W_cat  = (const float*)d_in[11];
    const float* b_cat  = (const float*)d_in[12];
    const float* W_proj = (const float*)d_in[13];
    const float* b_proj = (const float*)d_in[14];
    const float* temp   = (const float*)d_in[15];
    float* out = (float*)d_out;

    float *p_bq, *p_ssq, *p_ssk, *p_bfin;
    __half *p_qh, *p_kh, *p_xyT, *p_zT, *p_WqA, *p_Wk, *p_WfA;
    cudaGetSymbolAddress((void**)&p_qh,   g_qh);
    cudaGetSymbolAddress((void**)&p_kh,   g_kh);
    cudaGetSymbolAddress((void**)&p_bq,   g_bq);
    cudaGetSymbolAddress((void**)&p_ssq,  g_ssq_q);
    cudaGetSymbolAddress((void**)&p_ssk,  g_ssq_k);
    cudaGetSymbolAddress((void**)&p_bfin, g_bfin);
    cudaGetSymbolAddress((void**)&p_xyT,  g_xyT);
    cudaGetSymbolAddress((void**)&p_zT,   g_zT);
    cudaGetSymbolAddress((void**)&p_WqA,  g_WqA);
    cudaGetSymbolAddress((void**)&p_Wk,   g_Wk);
    cudaGetSymbolAddress((void**)&p_WfA,  g_WfA);

    cudaFuncSetAttribute(gemm_mma, cudaFuncAttributeMaxDynamicSharedMemorySize, SMEM_GEMM);

    dim3 gg(C_ / 128, HW_ / 128, B_);   // (2, 72, 8)

    convert_T<<<dim3(HW_ / 64, C_ / 32, B_ * 3), 256>>>(x, y, z);              // 0
    cvtK_w<<<256, 256>>>(W_kf);                                                // 1
    zero_kernel<<<(B_ * C_ + 255) / 256, 256>>>();                             // 2
    gemm_mma<<<gg, 256, SMEM_GEMM>>>(p_Wk, 0, p_zT, 256,                       // 3
                                     b_kf, 0, nullptr, p_kh, nullptr, p_ssk);
    fold_weights<<<256, 256>>>(W_cat, W_qr, W_qd, b_qr, b_qd, b_cat);          // 4
    cvtQ_w<<<dim3(256, 2), 256>>>();                                           // 5
    gemm_mma<<<gg, 256, SMEM_GEMM>>>(p_WqA, 0, p_xyT, 512,                     // 6
                                     p_bq, 0, nullptr, p_qh, nullptr, p_ssq);

    attn_s_mma<<<dim3(HEADS, B_, SPLITS), 128>>>();
    softmax_kernel<<<B_ * HEADS, 32>>>(temp);
    mfuse_kernel<<<dim3(HEADS, B_), 256>>>(W_proj);
    wfinal_kernel<<<dim3(32, B_), 256>>>(W_vf, b_vf, b_proj);
    cvtF_w<<<B_ * 256, 256>>>();

    gemm_mma<<<gg, 256, SMEM_GEMM>>>(p_WfA, (long)C_ * C_, p_zT, 256,
                                     p_bfin, C_, out, nullptr, z, nullptr);
}